// round 4
// baseline (speedup 1.0000x reference)
#include <cuda_runtime.h>
#include <math.h>

#define Bb      128
#define Ll      2048
#define NOBS    32
#define NHID    512
#define NSTEPS  (Ll - 1)          // 2047
#define NCTA    128
#define NTHREADS 256
#define NBARS   (NSTEPS - 1)
typedef unsigned long long u64;
#define BARMOD  ((u64)NBARS * NCTA)

// SMEM: A-dup [32 cols][514 u64], x [8 pairs][514 u64]
#define SA_STRIDE 514
#define SA_U64    (32 * SA_STRIDE)           // 16448 u64
#define SX_STRIDE 514
#define SX_U64    (8 * SX_STRIDE)            // 4112 u64
#define SMEM_BYTES ((SA_U64 + SX_U64) * 8)   // 164480 B

__device__ u64 g_count;   // monotonic grid-barrier counter

// ---------------------------------------------------------------------------
__device__ __forceinline__ u64 pack2(float a, float b) {
    u64 r;
    asm("mov.b64 %0, {%1, %2};" : "=l"(r) : "f"(a), "f"(b));
    return r;
}
__device__ __forceinline__ void unpack2(u64 v, float& a, float& b) {
    asm("mov.b64 {%0, %1}, %2;" : "=f"(a), "=f"(b) : "l"(v));
}
__device__ __forceinline__ void ffma2(u64& acc, u64 a, u64 x) {
    asm("fma.rn.f32x2 %0, %1, %2, %0;" : "+l"(acc) : "l"(a), "l"(x));
}

// XLA EmitFastTanh (fma path) — verified bit-exact in R3. DO NOT CHANGE.
__device__ __forceinline__ float tanh_xla(float x) {
    const float kClamp = 7.99881172180175781f;
    float xc = fminf(fmaxf(x, -kClamp), kClamp);
    float x2 = __fmul_rn(xc, xc);
    float num = -2.76076847742355e-16f;
    num = fmaf(x2, num, 2.00018790482477e-13f);
    num = fmaf(x2, num, -8.60467152213735e-11f);
    num = fmaf(x2, num, 5.12229709037114e-08f);
    num = fmaf(x2, num, 1.48572235717979e-05f);
    num = fmaf(x2, num, 6.37261928875436e-04f);
    num = fmaf(x2, num, 4.89352455891786e-03f);
    num = __fmul_rn(xc, num);
    float den = 1.19825839466702e-06f;
    den = fmaf(x2, den, 1.18534705686654e-04f);
    den = fmaf(x2, den, 2.26843463243900e-03f);
    den = fmaf(x2, den, 4.89352518554385e-03f);
    float r = __fdiv_rn(num, den);
    return (fabsf(x) < 0.0004f) ? x : r;
}

__device__ __forceinline__ void grid_barrier(u64 target) {
    __syncthreads();
    if (threadIdx.x == 0) {
        __threadfence();
        atomicAdd(&g_count, 1ULL);
        u64 v;
        do {
            asm volatile("ld.global.acquire.gpu.u64 %0, [%1];"
                         : "=l"(v) : "l"(&g_count));
        } while (v < target);
    }
    __syncthreads();
}

// ---------------------------------------------------------------------------
// Persistent HCNN scan, order-exact fp32.
// 128 CTAs = 16 n-tiles (32 cols) x 8 m-tiles (16 batches = 8 pairs).
// 256 threads = 8 warps. Staging: warp w stages pair w. Compute: lane =
// (pair p = lane&7, col-idx ci = lane>>3); warp w owns cols n0+4w..n0+4w+3.
// One full ascending-k f32x2 chain per thread.
// ---------------------------------------------------------------------------
__global__ void __launch_bounds__(NTHREADS, 1) ptf_persistent(
    const float* __restrict__ data,   // [B, L, NOBS]
    const float* __restrict__ Amat,   // [NHID, NHID]
    const float* __restrict__ h0,     // [NHID]
    float* __restrict__ exps,
    float* __restrict__ states,       // doubles as the recurrent state
    float* __restrict__ deltas,
    float* __restrict__ partials)
{
    extern __shared__ u64 smem[];
    u64* sA = smem;                   // [32][SA_STRIDE] (a,a) dup pairs
    u64* sx = smem + SA_U64;          // [8][SX_STRIDE]  (vA,vB) pairs

    const int tid = threadIdx.x;
    const int w   = tid >> 5;                 // warp 0..7
    const int l   = tid & 31;
    const int nt  = blockIdx.x & 15;
    const int mt  = blockIdx.x >> 4;
    const int n0  = nt * 32;
    const int m0  = mt * 16;

    // ---- barrier base first (before any long work; monotonic counter) ----
    u64 base;
    {
        u64 v;
        asm volatile("ld.global.acquire.gpu.u64 %0, [%1];" : "=l"(v) : "l"(&g_count));
        base = v - (v % BARMOD);
    }

    // ---- one-time: A rows n0..n0+31 -> SMEM, duplicated (a,a) ----
    for (int i = tid; i < 32 * 128; i += NTHREADS) {      // float4 chunks
        int col = i >> 7;
        int kq  = (i & 127) * 4;
        float4 a = *(const float4*)&Amat[(size_t)(n0 + col) * NHID + kq];
        u64* dst = &sA[(size_t)col * SA_STRIDE + kq];
        dst[0] = pack2(a.x, a.x);
        dst[1] = pack2(a.y, a.y);
        dst[2] = pack2(a.z, a.z);
        dst[3] = pack2(a.w, a.w);
    }
    __syncthreads();

    // compute-phase identifiers
    const int p   = l & 7;                    // pair 0..7
    const int ci  = l >> 3;                   // 0..3
    const int n   = n0 + (w << 2) + ci;       // this thread's column
    const int cbA = m0 + p;                   // compute batch rows
    const int cbB = cbA + 8;
    const u64* xr = sx + (size_t)p * SX_STRIDE;
    const u64* ar = sA + (size_t)((w << 2) + ci) * SA_STRIDE;

    // staging identifiers: warp w stages pair w (rows sbA, sbB)
    const int sbA = m0 + w;
    const int sbB = sbA + 8;

    for (int t = 0; t < NSTEPS; t++) {
        // ---------------- stage state pairs (+ exact injection + outputs) ----
        #pragma unroll
        for (int j = 0; j < 4; j++) {
            const int k0 = 4 * l + 128 * j;
            const float* srcA = (t == 0) ? (h0 + k0)
                              : (states + ((size_t)sbA * Ll + t) * NHID + k0);
            const float* srcB = (t == 0) ? (h0 + k0)
                              : (states + ((size_t)sbB * Ll + t) * NHID + k0);
            float4 a4 = *(const float4*)srcA;
            float4 b4 = *(const float4*)srcB;

            if (t == 0 && nt == 0) {          // states[:,0,:] = s0 (pre-inject)
                *(float4*)&states[((size_t)sbA * Ll) * NHID + k0] = a4;
                *(float4*)&states[((size_t)sbB * Ll) * NHID + k0] = b4;
            }
            if (k0 < NOBS) {                  // teacher forcing: s + (y - s)
                float4 yA = *(const float4*)&data[((size_t)sbA * Ll + t) * NOBS + k0];
                float4 yB = *(const float4*)&data[((size_t)sbB * Ll + t) * NOBS + k0];
                float4 dA, dB;
                dA.x = __fsub_rn(yA.x, a4.x); dA.y = __fsub_rn(yA.y, a4.y);
                dA.z = __fsub_rn(yA.z, a4.z); dA.w = __fsub_rn(yA.w, a4.w);
                dB.x = __fsub_rn(yB.x, b4.x); dB.y = __fsub_rn(yB.y, b4.y);
                dB.z = __fsub_rn(yB.z, b4.z); dB.w = __fsub_rn(yB.w, b4.w);
                if (nt == 0) {
                    size_t oA = ((size_t)sbA * Ll + t) * NOBS + k0;
                    size_t oB = ((size_t)sbB * Ll + t) * NOBS + k0;
                    *(float4*)&exps[oA] = a4;  *(float4*)&exps[oB] = b4;
                    *(float4*)&deltas[oA]   = dA; *(float4*)&deltas[oB]   = dB;
                    *(float4*)&partials[oA] = dA; *(float4*)&partials[oB] = dB;
                }
                a4.x = __fadd_rn(a4.x, dA.x); a4.y = __fadd_rn(a4.y, dA.y);
                a4.z = __fadd_rn(a4.z, dA.z); a4.w = __fadd_rn(a4.w, dA.w);
                b4.x = __fadd_rn(b4.x, dB.x); b4.y = __fadd_rn(b4.y, dB.y);
                b4.z = __fadd_rn(b4.z, dB.z); b4.w = __fadd_rn(b4.w, dB.w);
            }
            u64* dst = &sx[(size_t)w * SX_STRIDE + k0];
            dst[0] = pack2(a4.x, b4.x);
            dst[1] = pack2(a4.y, b4.y);
            dst[2] = pack2(a4.z, b4.z);
            dst[3] = pack2(a4.w, b4.w);
        }
        __syncthreads();

        // -------- compute: one full ascending-k chain per thread ----------
        u64 acc = 0;                          // both lanes 0.0f
        #pragma unroll 8
        for (int k = 0; k < NHID; k += 2) {
            ulonglong2 X  = *(const ulonglong2*)(xr + k);   // 8-distinct bc
            ulonglong2 Aq = *(const ulonglong2*)(ar + k);   // 4-distinct bc
            ffma2(acc, Aq.x, X.x);
            ffma2(acc, Aq.y, X.y);
        }

        float zA, zB;
        unpack2(acc, zA, zB);
        const float hA = tanh_xla(zA);
        const float hB = tanh_xla(zB);

        states[((size_t)cbA * Ll + t + 1) * NHID + n] = hA;
        states[((size_t)cbB * Ll + t + 1) * NHID + n] = hB;

        if (t == NSTEPS - 1 && nt == 0) {     // n < 32 for all threads here
            size_t oA = ((size_t)cbA * Ll + (Ll - 1)) * NOBS + n;
            size_t oB = ((size_t)cbB * Ll + (Ll - 1)) * NOBS + n;
            exps[oA] = hA;  exps[oB] = hB;
            float dA = __fsub_rn(data[((size_t)cbA * Ll + (Ll - 2)) * NOBS + n], hA);
            float dB = __fsub_rn(data[((size_t)cbB * Ll + (Ll - 2)) * NOBS + n], hB);
            deltas[oA] = dA; partials[oA] = dA;
            deltas[oB] = dB; partials[oB] = dB;
        }

        if (t < NSTEPS - 1)
            grid_barrier(base + (u64)(t + 1) * NCTA);
    }
}

// ---------------------------------------------------------------------------
extern "C" void kernel_launch(void* const* d_in, const int* in_sizes, int n_in,
                              void* d_out, int out_size) {
    const float* data = (const float*)d_in[0];  // [128,2048,32]
    const float* A    = (const float*)d_in[1];  // [512,512]
    const float* h0   = (const float*)d_in[2];  // [1,512]
    // d_in[3] = prob (0) -> dropout identity

    float* out      = (float*)d_out;
    float* exps     = out;
    float* states   = exps   + (size_t)Bb * Ll * NOBS;
    float* deltas   = states + (size_t)Bb * Ll * NHID;
    float* partials = deltas + (size_t)Bb * Ll * NOBS;

    cudaFuncSetAttribute(ptf_persistent,
                         cudaFuncAttributeMaxDynamicSharedMemorySize, SMEM_BYTES);
    ptf_persistent<<<NCTA, NTHREADS, SMEM_BYTES>>>(data, A, h0,
                                                   exps, states, deltas, partials);
}

// round 6
// speedup vs baseline: 1.4018x; 1.4018x over previous
#include <cuda_runtime.h>
#include <math.h>

#define Bb      128
#define Ll      2048
#define NOBS    32
#define NHID    512
#define NSTEPS  (Ll - 1)          // 2047
#define NCTA    128
#define NTHREADS 128
#define NBARS   (NSTEPS - 1)
typedef unsigned long long u64;
#define BARMOD  ((u64)NBARS * NCTA)

// SMEM: A transposed [512][34] floats (EVEN stride -> 8B-aligned float2)
//       + X pair-major [8][514] u64
#define SAT_STRIDE 34
#define SAT_FLOATS (NHID * SAT_STRIDE)          // 17408 floats = 69632 B
#define SX_STRIDE  514                          // u64 rows (4112 B, 16B-aligned)
#define SX_U64     (8 * SX_STRIDE)
#define SMEM_BYTES (SAT_FLOATS * 4 + SX_U64 * 8)  // 69632 + 32896 = 102528 B

__device__ u64 g_count;   // monotonic grid-barrier counter

// ---------------------------------------------------------------------------
__device__ __forceinline__ u64 pack2(float a, float b) {
    u64 r;
    asm("mov.b64 %0, {%1, %2};" : "=l"(r) : "f"(a), "f"(b));
    return r;
}
__device__ __forceinline__ void unpack2(u64 v, float& a, float& b) {
    asm("mov.b64 {%0, %1}, %2;" : "=f"(a), "=f"(b) : "l"(v));
}
__device__ __forceinline__ void ffma2(u64& acc, u64 a, u64 x) {
    asm("fma.rn.f32x2 %0, %1, %2, %0;" : "+l"(acc) : "l"(a), "l"(x));
}

// XLA EmitFastTanh (fma path) — verified bit-exact (rel_err 0.0). DO NOT CHANGE.
__device__ __forceinline__ float tanh_xla(float x) {
    const float kClamp = 7.99881172180175781f;
    float xc = fminf(fmaxf(x, -kClamp), kClamp);
    float x2 = __fmul_rn(xc, xc);
    float num = -2.76076847742355e-16f;
    num = fmaf(x2, num, 2.00018790482477e-13f);
    num = fmaf(x2, num, -8.60467152213735e-11f);
    num = fmaf(x2, num, 5.12229709037114e-08f);
    num = fmaf(x2, num, 1.48572235717979e-05f);
    num = fmaf(x2, num, 6.37261928875436e-04f);
    num = fmaf(x2, num, 4.89352455891786e-03f);
    num = __fmul_rn(xc, num);
    float den = 1.19825839466702e-06f;
    den = fmaf(x2, den, 1.18534705686654e-04f);
    den = fmaf(x2, den, 2.26843463243900e-03f);
    den = fmaf(x2, den, 4.89352518554385e-03f);
    float r = __fdiv_rn(num, den);
    return (fabsf(x) < 0.0004f) ? x : r;
}

__device__ __forceinline__ void grid_barrier(u64 target) {
    __syncthreads();
    if (threadIdx.x == 0) {
        __threadfence();
        atomicAdd(&g_count, 1ULL);
        u64 v;
        do {
            asm volatile("ld.global.acquire.gpu.u64 %0, [%1];"
                         : "=l"(v) : "l"(&g_count));
        } while (v < target);
    }
    __syncthreads();
}

// ---------------------------------------------------------------------------
// Persistent HCNN scan, order-exact fp32, crossbar-optimized.
// 128 CTAs = 16 n-tiles (32 cols) x 8 m-tiles (16 batches = 8 pairs).
// 128 threads: all 4 warps stage; warps 0-1 compute with a 2-pair x 2-col
// register tile per thread (6 B loaded per FMA2 -> ~6144 cyc crossbar floor).
// ---------------------------------------------------------------------------
__global__ void __launch_bounds__(NTHREADS, 1) ptf_persistent(
    const float* __restrict__ data,   // [B, L, NOBS]
    const float* __restrict__ Amat,   // [NHID, NHID]
    const float* __restrict__ h0,     // [NHID]
    float* __restrict__ exps,
    float* __restrict__ states,       // doubles as the recurrent state
    float* __restrict__ deltas,
    float* __restrict__ partials)
{
    extern __shared__ char smem_raw[];
    float* sAT = (float*)smem_raw;                        // [512][34]
    u64*   sx  = (u64*)(smem_raw + SAT_FLOATS * 4);       // [8][514]

    const int tid = threadIdx.x;
    const int w   = tid >> 5;                 // warp 0..3
    const int l   = tid & 31;
    const int nt  = blockIdx.x & 15;
    const int mt  = blockIdx.x >> 4;
    const int n0  = nt * 32;
    const int m0  = mt * 16;

    // ---- barrier base (monotonic counter across graph replays) ----
    u64 base;
    {
        u64 v;
        asm volatile("ld.global.acquire.gpu.u64 %0, [%1];" : "=l"(v) : "l"(&g_count));
        base = v - (v % BARMOD);
    }

    // ---- one-time: A rows n0..n0+31 -> sAT[k][c] transposed (stride 34) ----
    {
        const int c = tid & 31;
        for (int it = 0; it < 32; it++) {
            const int k0 = ((tid >> 5) + 4 * it) * 4;
            float4 a = *(const float4*)&Amat[(size_t)(n0 + c) * NHID + k0];
            sAT[(k0 + 0) * SAT_STRIDE + c] = a.x;
            sAT[(k0 + 1) * SAT_STRIDE + c] = a.y;
            sAT[(k0 + 2) * SAT_STRIDE + c] = a.z;
            sAT[(k0 + 3) * SAT_STRIDE + c] = a.w;
        }
    }
    __syncthreads();

    // compute-thread identifiers (warps 0,1 only)
    const int cp  = l & 15;                   // col-pair 0..15
    const int pg  = (l >> 4) + 2 * w;         // pair-group 0..3 (valid for w<2)
    const int pA  = 2 * pg;                   // pairs pA, pA+1
    const int nA  = n0 + 2 * cp;              // cols nA, nA+1
    const u64* xrA = sx + (size_t)pA * SX_STRIDE;
    const u64* xrB = sx + (size_t)(pA + 1) * SX_STRIDE;

    for (int t = 0; t < NSTEPS; t++) {
        // ---------------- stage state pairs (+ exact injection + outputs) ----
        // warp w stages pairs w and w+4; 4 float4-chunks per pair per thread
        #pragma unroll
        for (int r = 0; r < 2; r++) {
            const int p   = w + 4 * r;
            const int sbA = m0 + p;
            const int sbB = sbA + 8;
            #pragma unroll
            for (int j = 0; j < 4; j++) {
                const int k0 = 4 * l + 128 * j;
                const float* srcA = (t == 0) ? (h0 + k0)
                                  : (states + ((size_t)sbA * Ll + t) * NHID + k0);
                const float* srcB = (t == 0) ? (h0 + k0)
                                  : (states + ((size_t)sbB * Ll + t) * NHID + k0);
                float4 a4 = *(const float4*)srcA;
                float4 b4 = *(const float4*)srcB;

                if (t == 0 && nt == 0) {      // states[:,0,:] = s0 (pre-inject)
                    *(float4*)&states[((size_t)sbA * Ll) * NHID + k0] = a4;
                    *(float4*)&states[((size_t)sbB * Ll) * NHID + k0] = b4;
                }
                if (k0 < NOBS) {              // teacher forcing: s + (y - s)
                    float4 yA = *(const float4*)&data[((size_t)sbA * Ll + t) * NOBS + k0];
                    float4 yB = *(const float4*)&data[((size_t)sbB * Ll + t) * NOBS + k0];
                    float4 dA, dB;
                    dA.x = __fsub_rn(yA.x, a4.x); dA.y = __fsub_rn(yA.y, a4.y);
                    dA.z = __fsub_rn(yA.z, a4.z); dA.w = __fsub_rn(yA.w, a4.w);
                    dB.x = __fsub_rn(yB.x, b4.x); dB.y = __fsub_rn(yB.y, b4.y);
                    dB.z = __fsub_rn(yB.z, b4.z); dB.w = __fsub_rn(yB.w, b4.w);
                    if (nt == 0) {
                        size_t oA = ((size_t)sbA * Ll + t) * NOBS + k0;
                        size_t oB = ((size_t)sbB * Ll + t) * NOBS + k0;
                        *(float4*)&exps[oA] = a4;  *(float4*)&exps[oB] = b4;
                        *(float4*)&deltas[oA]   = dA; *(float4*)&deltas[oB]   = dB;
                        *(float4*)&partials[oA] = dA; *(float4*)&partials[oB] = dB;
                    }
                    a4.x = __fadd_rn(a4.x, dA.x); a4.y = __fadd_rn(a4.y, dA.y);
                    a4.z = __fadd_rn(a4.z, dA.z); a4.w = __fadd_rn(a4.w, dA.w);
                    b4.x = __fadd_rn(b4.x, dB.x); b4.y = __fadd_rn(b4.y, dB.y);
                    b4.z = __fadd_rn(b4.z, dB.z); b4.w = __fadd_rn(b4.w, dB.w);
                }
                u64* dst = &sx[(size_t)p * SX_STRIDE + k0];
                ulonglong2 lo, hi;
                lo.x = pack2(a4.x, b4.x); lo.y = pack2(a4.y, b4.y);
                hi.x = pack2(a4.z, b4.z); hi.y = pack2(a4.w, b4.w);
                *(ulonglong2*)(dst)     = lo;
                *(ulonglong2*)(dst + 2) = hi;
            }
        }
        __syncthreads();

        // -------- compute (warps 0,1): 2x2 register tile, ascending-k chains --
        if (w < 2) {
            u64 acc00 = 0, acc01 = 0, acc10 = 0, acc11 = 0;
            #pragma unroll 8
            for (int k = 0; k < NHID; k++) {
                u64 x0 = xrA[k];                               // LDS.64 broadcast
                u64 x1 = xrB[k];                               // LDS.64 broadcast
                float2 a = *(const float2*)&sAT[k * SAT_STRIDE + 2 * cp]; // aligned
                u64 a0 = pack2(a.x, a.x);
                u64 a1 = pack2(a.y, a.y);
                ffma2(acc00, a0, x0);   // col nA,   pair pA
                ffma2(acc01, a0, x1);   // col nA,   pair pA+1
                ffma2(acc10, a1, x0);   // col nA+1, pair pA
                ffma2(acc11, a1, x1);   // col nA+1, pair pA+1
            }

            float z00a, z00b, z01a, z01b, z10a, z10b, z11a, z11b;
            unpack2(acc00, z00a, z00b);
            unpack2(acc01, z01a, z01b);
            unpack2(acc10, z10a, z10b);
            unpack2(acc11, z11a, z11b);
            // batches: pair p -> (m0+p, m0+p+8)
            const int b0 = m0 + pA;           // acc*0a
            const int b1 = b0 + 8;            // acc*0b
            const int b2 = m0 + pA + 1;       // acc*1a
            const int b3 = b2 + 8;            // acc*1b
            float h00 = tanh_xla(z00a), h01 = tanh_xla(z00b);
            float h02 = tanh_xla(z01a), h03 = tanh_xla(z01b);
            float h10 = tanh_xla(z10a), h11 = tanh_xla(z10b);
            float h12 = tanh_xla(z11a), h13 = tanh_xla(z11b);

            // states writes: per batch, cols (nA, nA+1) adjacent -> STG.64
            float* so = states + ((size_t)t + 1) * NHID + nA;  // + b*Ll*NHID
            *(float2*)(so + (size_t)b0 * Ll * NHID) = make_float2(h00, h10);
            *(float2*)(so + (size_t)b1 * Ll * NHID) = make_float2(h01, h11);
            *(float2*)(so + (size_t)b2 * Ll * NHID) = make_float2(h02, h12);
            *(float2*)(so + (size_t)b3 * Ll * NHID) = make_float2(h03, h13);

            if (t == NSTEPS - 1 && nt == 0) {   // nA, nA+1 < 32 here
                const int   bs[4] = {b0, b1, b2, b3};
                const float hx[4] = {h00, h01, h02, h03};   // col nA
                const float hy[4] = {h10, h11, h12, h13};   // col nA+1
                #pragma unroll
                for (int i = 0; i < 4; i++) {
                    size_t o  = ((size_t)bs[i] * Ll + (Ll - 1)) * NOBS + nA;
                    size_t dI = ((size_t)bs[i] * Ll + (Ll - 2)) * NOBS + nA;
                    exps[o]     = hx[i];
                    exps[o + 1] = hy[i];
                    float dx = __fsub_rn(data[dI],     hx[i]);
                    float dy = __fsub_rn(data[dI + 1], hy[i]);
                    deltas[o]       = dx; deltas[o + 1]   = dy;
                    partials[o]     = dx; partials[o + 1] = dy;
                }
            }
        }

        if (t < NSTEPS - 1)
            grid_barrier(base + (u64)(t + 1) * NCTA);
    }
}

// ---------------------------------------------------------------------------
extern "C" void kernel_launch(void* const* d_in, const int* in_sizes, int n_in,
                              void* d_out, int out_size) {
    const float* data = (const float*)d_in[0];  // [128,2048,32]
    const float* A    = (const float*)d_in[1];  // [512,512]
    const float* h0   = (const float*)d_in[2];  // [1,512]
    // d_in[3] = prob (0) -> dropout identity

    float* out      = (float*)d_out;
    float* exps     = out;
    float* states   = exps   + (size_t)Bb * Ll * NOBS;
    float* deltas   = states + (size_t)Bb * Ll * NHID;
    float* partials = deltas + (size_t)Bb * Ll * NOBS;

    cudaFuncSetAttribute(ptf_persistent,
                         cudaFuncAttributeMaxDynamicSharedMemorySize, SMEM_BYTES);
    ptf_persistent<<<NCTA, NTHREADS, SMEM_BYTES>>>(data, A, h0,
                                                   exps, states, deltas, partials);
}

// round 7
// speedup vs baseline: 1.5719x; 1.1213x over previous
#include <cuda_runtime.h>
#include <math.h>

#define Bb      128
#define Ll      2048
#define NOBS    32
#define NHID    512
#define NSTEPS  (Ll - 1)          // 2047
#define NCTA    128
#define NTHREADS 128
#define NBARS   (NSTEPS - 1)
typedef unsigned long long u64;
#define BARMOD  ((u64)NBARS * NCTA)

// SMEM: A interleaved [256 k2][16 cp][4 floats] + X pair-major [8][514] u64
#define SA2_FLOATS (256 * 16 * 4)               // 16384 floats = 65536 B
#define SX_STRIDE  514                          // u64 rows (4112 B, 16B-aligned)
#define SX_U64     (8 * SX_STRIDE)
#define SMEM_BYTES (SA2_FLOATS * 4 + SX_U64 * 8)  // 65536 + 32896 = 98432 B

__device__ u64 g_count;   // monotonic grid-barrier counter

// ---------------------------------------------------------------------------
__device__ __forceinline__ u64 pack2(float a, float b) {
    u64 r;
    asm("mov.b64 %0, {%1, %2};" : "=l"(r) : "f"(a), "f"(b));
    return r;
}
__device__ __forceinline__ void unpack2(u64 v, float& a, float& b) {
    asm("mov.b64 {%0, %1}, %2;" : "=f"(a), "=f"(b) : "l"(v));
}
__device__ __forceinline__ void ffma2(u64& acc, u64 a, u64 x) {
    asm("fma.rn.f32x2 %0, %1, %2, %0;" : "+l"(acc) : "l"(a), "l"(x));
}

// XLA EmitFastTanh (fma path) — verified bit-exact (rel_err 0.0). DO NOT CHANGE.
__device__ __forceinline__ float tanh_xla(float x) {
    const float kClamp = 7.99881172180175781f;
    float xc = fminf(fmaxf(x, -kClamp), kClamp);
    float x2 = __fmul_rn(xc, xc);
    float num = -2.76076847742355e-16f;
    num = fmaf(x2, num, 2.00018790482477e-13f);
    num = fmaf(x2, num, -8.60467152213735e-11f);
    num = fmaf(x2, num, 5.12229709037114e-08f);
    num = fmaf(x2, num, 1.48572235717979e-05f);
    num = fmaf(x2, num, 6.37261928875436e-04f);
    num = fmaf(x2, num, 4.89352455891786e-03f);
    num = __fmul_rn(xc, num);
    float den = 1.19825839466702e-06f;
    den = fmaf(x2, den, 1.18534705686654e-04f);
    den = fmaf(x2, den, 2.26843463243900e-03f);
    den = fmaf(x2, den, 4.89352518554385e-03f);
    float r = __fdiv_rn(num, den);
    return (fabsf(x) < 0.0004f) ? x : r;
}

__device__ __forceinline__ void grid_barrier(u64 target) {
    __syncthreads();
    if (threadIdx.x == 0) {
        __threadfence();
        atomicAdd(&g_count, 1ULL);
        u64 v;
        do {
            asm volatile("ld.global.acquire.gpu.u64 %0, [%1];"
                         : "=l"(v) : "l"(&g_count));
        } while (v < target);
    }
    __syncthreads();
}

// ---------------------------------------------------------------------------
// Persistent HCNN scan, order-exact fp32.
// 128 CTAs = 16 n-tiles (32 cols) x 8 m-tiles (16 batches = 8 pairs).
// 128 threads = 4 warps, ALL compute: thread tile = 1 pair x 2 cols
// (p = tid&7, cp = tid>>3). Per 2k: 1 LDS.128 x + 1 LDS.128 a + 4 FFMA2.
// Crossbar floor 8192 cyc/step spread over all 4 SMSPs.
// ---------------------------------------------------------------------------
__global__ void __launch_bounds__(NTHREADS, 1) ptf_persistent(
    const float* __restrict__ data,   // [B, L, NOBS]
    const float* __restrict__ Amat,   // [NHID, NHID]
    const float* __restrict__ h0,     // [NHID]
    float* __restrict__ exps,
    float* __restrict__ states,       // doubles as the recurrent state
    float* __restrict__ deltas,
    float* __restrict__ partials)
{
    extern __shared__ char smem_raw[];
    float* sA2 = (float*)smem_raw;                        // [256][16][4]
    u64*   sx  = (u64*)(smem_raw + SA2_FLOATS * 4);       // [8][514]

    const int tid = threadIdx.x;
    const int w   = tid >> 5;                 // warp 0..3
    const int l   = tid & 31;
    const int nt  = blockIdx.x & 15;
    const int mt  = blockIdx.x >> 4;
    const int n0  = nt * 32;
    const int m0  = mt * 16;

    // ---- barrier base (monotonic counter across graph replays) ----
    u64 base;
    {
        u64 v;
        asm volatile("ld.global.acquire.gpu.u64 %0, [%1];" : "=l"(v) : "l"(&g_count));
        base = v - (v % BARMOD);
    }

    // ---- one-time: A -> sA2[k2][cp][4] = {a_n[2k2], a_n[2k2+1],
    //                                       a_n1[2k2], a_n1[2k2+1]} ----
    for (int i = tid; i < 256 * 16; i += NTHREADS) {
        const int k2 = i >> 4;           // 0..255
        const int cp = i & 15;           // 0..15
        const int n  = n0 + 2 * cp;
        float2 a0 = *(const float2*)&Amat[(size_t)n * NHID + 2 * k2];
        float2 a1 = *(const float2*)&Amat[(size_t)(n + 1) * NHID + 2 * k2];
        float4 v  = make_float4(a0.x, a0.y, a1.x, a1.y);
        *(float4*)&sA2[(size_t)i * 4] = v;
    }
    __syncthreads();

    // compute-thread identifiers
    const int p   = tid & 7;                  // pair 0..7
    const int cp  = tid >> 3;                 // col-pair 0..15
    const int nA  = n0 + 2 * cp;              // cols nA, nA+1
    const int bA  = m0 + p;                   // batches bA, bA+8
    const int bB  = bA + 8;
    const u64* xr = sx + (size_t)p * SX_STRIDE;

    for (int t = 0; t < NSTEPS; t++) {
        // ---------------- stage state pairs (+ exact injection + outputs) ----
        // warp w stages pairs w and w+4; 4 float4-chunks per pair per thread
        #pragma unroll
        for (int r = 0; r < 2; r++) {
            const int sp  = w + 4 * r;
            const int sbA = m0 + sp;
            const int sbB = sbA + 8;
            #pragma unroll
            for (int j = 0; j < 4; j++) {
                const int k0 = 4 * l + 128 * j;
                const float* srcA = (t == 0) ? (h0 + k0)
                                  : (states + ((size_t)sbA * Ll + t) * NHID + k0);
                const float* srcB = (t == 0) ? (h0 + k0)
                                  : (states + ((size_t)sbB * Ll + t) * NHID + k0);
                float4 a4 = *(const float4*)srcA;
                float4 b4 = *(const float4*)srcB;

                if (t == 0 && nt == 0) {      // states[:,0,:] = s0 (pre-inject)
                    *(float4*)&states[((size_t)sbA * Ll) * NHID + k0] = a4;
                    *(float4*)&states[((size_t)sbB * Ll) * NHID + k0] = b4;
                }
                if (k0 < NOBS) {              // teacher forcing: s + (y - s)
                    float4 yA = *(const float4*)&data[((size_t)sbA * Ll + t) * NOBS + k0];
                    float4 yB = *(const float4*)&data[((size_t)sbB * Ll + t) * NOBS + k0];
                    float4 dA, dB;
                    dA.x = __fsub_rn(yA.x, a4.x); dA.y = __fsub_rn(yA.y, a4.y);
                    dA.z = __fsub_rn(yA.z, a4.z); dA.w = __fsub_rn(yA.w, a4.w);
                    dB.x = __fsub_rn(yB.x, b4.x); dB.y = __fsub_rn(yB.y, b4.y);
                    dB.z = __fsub_rn(yB.z, b4.z); dB.w = __fsub_rn(yB.w, b4.w);
                    if (nt == 0) {
                        size_t oA = ((size_t)sbA * Ll + t) * NOBS + k0;
                        size_t oB = ((size_t)sbB * Ll + t) * NOBS + k0;
                        *(float4*)&exps[oA] = a4;  *(float4*)&exps[oB] = b4;
                        *(float4*)&deltas[oA]   = dA; *(float4*)&deltas[oB]   = dB;
                        *(float4*)&partials[oA] = dA; *(float4*)&partials[oB] = dB;
                    }
                    a4.x = __fadd_rn(a4.x, dA.x); a4.y = __fadd_rn(a4.y, dA.y);
                    a4.z = __fadd_rn(a4.z, dA.z); a4.w = __fadd_rn(a4.w, dA.w);
                    b4.x = __fadd_rn(b4.x, dB.x); b4.y = __fadd_rn(b4.y, dB.y);
                    b4.z = __fadd_rn(b4.z, dB.z); b4.w = __fadd_rn(b4.w, dB.w);
                }
                u64* dst = &sx[(size_t)sp * SX_STRIDE + k0];
                ulonglong2 lo, hi;
                lo.x = pack2(a4.x, b4.x); lo.y = pack2(a4.y, b4.y);
                hi.x = pack2(a4.z, b4.z); hi.y = pack2(a4.w, b4.w);
                *(ulonglong2*)(dst)     = lo;
                *(ulonglong2*)(dst + 2) = hi;
            }
        }
        __syncthreads();

        // -------- compute: 1 pair x 2 cols, ascending-k chains --------------
        u64 acc0 = 0, acc1 = 0;               // cols nA, nA+1 (both lanes 0.0f)
        #pragma unroll 8
        for (int k2 = 0; k2 < 256; k2++) {
            ulonglong2 X = *(const ulonglong2*)(xr + 2 * k2);      // x_k, x_k+1
            float4 a = *(const float4*)&sA2[(size_t)(k2 * 16 + cp) * 4];
            ffma2(acc0, pack2(a.x, a.x), X.x);   // col nA,   k
            ffma2(acc1, pack2(a.z, a.z), X.x);   // col nA+1, k
            ffma2(acc0, pack2(a.y, a.y), X.y);   // col nA,   k+1
            ffma2(acc1, pack2(a.w, a.w), X.y);   // col nA+1, k+1
        }

        float z0a, z0b, z1a, z1b;
        unpack2(acc0, z0a, z0b);              // (bA,nA), (bB,nA)
        unpack2(acc1, z1a, z1b);              // (bA,nA+1), (bB,nA+1)
        const float h00 = tanh_xla(z0a);
        const float h10 = tanh_xla(z1a);
        const float h01 = tanh_xla(z0b);
        const float h11 = tanh_xla(z1b);

        // states writes: per batch, cols (nA, nA+1) adjacent -> STG.64
        float* so = states + ((size_t)t + 1) * NHID + nA;
        *(float2*)(so + (size_t)bA * Ll * NHID) = make_float2(h00, h10);
        *(float2*)(so + (size_t)bB * Ll * NHID) = make_float2(h01, h11);

        if (t == NSTEPS - 1 && nt == 0) {     // nA, nA+1 < 32 here
            size_t oA = ((size_t)bA * Ll + (Ll - 1)) * NOBS + nA;
            size_t oB = ((size_t)bB * Ll + (Ll - 1)) * NOBS + nA;
            size_t dIA = ((size_t)bA * Ll + (Ll - 2)) * NOBS + nA;
            size_t dIB = ((size_t)bB * Ll + (Ll - 2)) * NOBS + nA;
            exps[oA] = h00; exps[oA + 1] = h10;
            exps[oB] = h01; exps[oB + 1] = h11;
            float dAx = __fsub_rn(data[dIA],     h00);
            float dAy = __fsub_rn(data[dIA + 1], h10);
            float dBx = __fsub_rn(data[dIB],     h01);
            float dBy = __fsub_rn(data[dIB + 1], h11);
            deltas[oA] = dAx; deltas[oA + 1] = dAy;
            deltas[oB] = dBx; deltas[oB + 1] = dBy;
            partials[oA] = dAx; partials[oA + 1] = dAy;
            partials[oB] = dBx; partials[oB + 1] = dBy;
        }

        if (t < NSTEPS - 1)
            grid_barrier(base + (u64)(t + 1) * NCTA);
    }
}

// ---------------------------------------------------------------------------
extern "C" void kernel_launch(void* const* d_in, const int* in_sizes, int n_in,
                              void* d_out, int out_size) {
    const float* data = (const float*)d_in[0];  // [128,2048,32]
    const float* A    = (const float*)d_in[1];  // [512,512]
    const float* h0   = (const float*)d_in[2];  // [1,512]
    // d_in[3] = prob (0) -> dropout identity

    float* out      = (float*)d_out;
    float* exps     = out;
    float* states   = exps   + (size_t)Bb * Ll * NOBS;
    float* deltas   = states + (size_t)Bb * Ll * NHID;
    float* partials = deltas + (size_t)Bb * Ll * NOBS;

    cudaFuncSetAttribute(ptf_persistent,
                         cudaFuncAttributeMaxDynamicSharedMemorySize, SMEM_BYTES);
    ptf_persistent<<<NCTA, NTHREADS, SMEM_BYTES>>>(data, A, h0,
                                                   exps, states, deltas, partials);
}

// round 8
// speedup vs baseline: 1.6726x; 1.0641x over previous
#include <cuda_runtime.h>
#include <math.h>

#define Bb      128
#define Ll      2048
#define NOBS    32
#define NHID    512
#define NSTEPS  (Ll - 1)          // 2047
#define NCTA    128
#define NTHREADS 128
#define NBARS   (NSTEPS - 1)
typedef unsigned long long u64;
#define GRP_CTAS 16               // CTAs per m-tile group
#define BARMOD  ((u64)NBARS * GRP_CTAS)

// SMEM: A interleaved [256 k2][16 cp][4 floats] + X pair-major [8][514] u64
#define SA2_FLOATS (256 * 16 * 4)               // 16384 floats = 65536 B
#define SX_STRIDE  514                          // u64 rows (4112 B, 16B-aligned)
#define SX_U64     (8 * SX_STRIDE)
#define SMEM_BYTES (SA2_FLOATS * 4 + SX_U64 * 8)  // 98432 B

// per-m-tile-group barrier counters, one 128B line each
__device__ u64 g_counts[8][16];

// ---------------------------------------------------------------------------
__device__ __forceinline__ u64 pack2(float a, float b) {
    u64 r;
    asm("mov.b64 %0, {%1, %2};" : "=l"(r) : "f"(a), "f"(b));
    return r;
}
__device__ __forceinline__ void unpack2(u64 v, float& a, float& b) {
    asm("mov.b64 {%0, %1}, %2;" : "=f"(a), "=f"(b) : "l"(v));
}
__device__ __forceinline__ void ffma2(u64& acc, u64 a, u64 x) {
    asm("fma.rn.f32x2 %0, %1, %2, %0;" : "+l"(acc) : "l"(a), "l"(x));
}

// XLA EmitFastTanh (fma path) — verified bit-exact (rel_err 0.0). DO NOT CHANGE.
__device__ __forceinline__ float tanh_xla(float x) {
    const float kClamp = 7.99881172180175781f;
    float xc = fminf(fmaxf(x, -kClamp), kClamp);
    float x2 = __fmul_rn(xc, xc);
    float num = -2.76076847742355e-16f;
    num = fmaf(x2, num, 2.00018790482477e-13f);
    num = fmaf(x2, num, -8.60467152213735e-11f);
    num = fmaf(x2, num, 5.12229709037114e-08f);
    num = fmaf(x2, num, 1.48572235717979e-05f);
    num = fmaf(x2, num, 6.37261928875436e-04f);
    num = fmaf(x2, num, 4.89352455891786e-03f);
    num = __fmul_rn(xc, num);
    float den = 1.19825839466702e-06f;
    den = fmaf(x2, den, 1.18534705686654e-04f);
    den = fmaf(x2, den, 2.26843463243900e-03f);
    den = fmaf(x2, den, 4.89352518554385e-03f);
    float r = __fdiv_rn(num, den);
    return (fabsf(x) < 0.0004f) ? x : r;
}

// group barrier: release-arrive + acquire-poll on the group's counter
__device__ __forceinline__ void group_barrier(u64* ctr, u64 target) {
    __syncthreads();
    if (threadIdx.x == 0) {
        asm volatile("red.global.release.gpu.add.u64 [%0], %1;"
                     :: "l"(ctr), "n"(1ULL) : "memory");
        u64 v;
        do {
            asm volatile("ld.global.acquire.gpu.u64 %0, [%1];"
                         : "=l"(v) : "l"(ctr));
        } while (v < target);
    }
    __syncthreads();
}

// ---------------------------------------------------------------------------
// Persistent HCNN scan, order-exact fp32.
// 128 CTAs = 16 n-tiles (32 cols) x 8 m-tile GROUPS (16 batches = 8 pairs).
// Sync is per m-tile group (16 CTAs): CTA (nt,mt) only ever reads states
// produced by CTAs (*, mt) -> groups progress independently.
// 128 threads = 4 warps, all compute: thread tile = 1 pair x 2 cols.
// ---------------------------------------------------------------------------
__global__ void __launch_bounds__(NTHREADS, 1) ptf_persistent(
    const float* __restrict__ data,   // [B, L, NOBS]
    const float* __restrict__ Amat,   // [NHID, NHID]
    const float* __restrict__ h0,     // [NHID]
    float* __restrict__ exps,
    float* __restrict__ states,       // doubles as the recurrent state
    float* __restrict__ deltas,
    float* __restrict__ partials)
{
    extern __shared__ char smem_raw[];
    float* sA2 = (float*)smem_raw;                        // [256][16][4]
    u64*   sx  = (u64*)(smem_raw + SA2_FLOATS * 4);       // [8][514]

    const int tid = threadIdx.x;
    const int w   = tid >> 5;                 // warp 0..3
    const int l   = tid & 31;
    const int nt  = blockIdx.x & 15;
    const int mt  = blockIdx.x >> 4;
    const int n0  = nt * 32;
    const int m0  = mt * 16;
    u64* ctr = &g_counts[mt][0];

    // ---- barrier base (monotonic counter across graph replays) ----
    u64 base;
    {
        u64 v;
        asm volatile("ld.global.acquire.gpu.u64 %0, [%1];" : "=l"(v) : "l"(ctr));
        base = v - (v % BARMOD);
    }

    // ---- one-time: A -> sA2[k2][cp][4] = {a_n[2k2], a_n[2k2+1],
    //                                       a_n1[2k2], a_n1[2k2+1]} ----
    for (int i = tid; i < 256 * 16; i += NTHREADS) {
        const int k2 = i >> 4;           // 0..255
        const int cp = i & 15;           // 0..15
        const int n  = n0 + 2 * cp;
        float2 a0 = *(const float2*)&Amat[(size_t)n * NHID + 2 * k2];
        float2 a1 = *(const float2*)&Amat[(size_t)(n + 1) * NHID + 2 * k2];
        float4 v  = make_float4(a0.x, a0.y, a1.x, a1.y);
        *(float4*)&sA2[(size_t)i * 4] = v;
    }
    __syncthreads();

    // compute-thread identifiers
    const int p   = tid & 7;                  // pair 0..7
    const int cp  = tid >> 3;                 // col-pair 0..15
    const int nA  = n0 + 2 * cp;              // cols nA, nA+1
    const int bA  = m0 + p;                   // batches bA, bA+8
    const int bB  = bA + 8;
    const u64* xr = sx + (size_t)p * SX_STRIDE;

    for (int t = 0; t < NSTEPS; t++) {
        // ---------------- stage state pairs (+ exact injection + outputs) ----
        // warp w stages pairs w and w+4; 4 float4-chunks per pair per thread
        #pragma unroll
        for (int r = 0; r < 2; r++) {
            const int sp  = w + 4 * r;
            const int sbA = m0 + sp;
            const int sbB = sbA + 8;
            #pragma unroll
            for (int j = 0; j < 4; j++) {
                const int k0 = 4 * l + 128 * j;
                const float* srcA = (t == 0) ? (h0 + k0)
                                  : (states + ((size_t)sbA * Ll + t) * NHID + k0);
                const float* srcB = (t == 0) ? (h0 + k0)
                                  : (states + ((size_t)sbB * Ll + t) * NHID + k0);
                float4 a4 = *(const float4*)srcA;
                float4 b4 = *(const float4*)srcB;

                if (t == 0 && nt == 0) {      // states[:,0,:] = s0 (pre-inject)
                    *(float4*)&states[((size_t)sbA * Ll) * NHID + k0] = a4;
                    *(float4*)&states[((size_t)sbB * Ll) * NHID + k0] = b4;
                }
                if (k0 < NOBS) {              // teacher forcing: s + (y - s)
                    float4 yA = *(const float4*)&data[((size_t)sbA * Ll + t) * NOBS + k0];
                    float4 yB = *(const float4*)&data[((size_t)sbB * Ll + t) * NOBS + k0];
                    float4 dA, dB;
                    dA.x = __fsub_rn(yA.x, a4.x); dA.y = __fsub_rn(yA.y, a4.y);
                    dA.z = __fsub_rn(yA.z, a4.z); dA.w = __fsub_rn(yA.w, a4.w);
                    dB.x = __fsub_rn(yB.x, b4.x); dB.y = __fsub_rn(yB.y, b4.y);
                    dB.z = __fsub_rn(yB.z, b4.z); dB.w = __fsub_rn(yB.w, b4.w);
                    if (nt == 0) {
                        size_t oA = ((size_t)sbA * Ll + t) * NOBS + k0;
                        size_t oB = ((size_t)sbB * Ll + t) * NOBS + k0;
                        *(float4*)&exps[oA] = a4;  *(float4*)&exps[oB] = b4;
                        *(float4*)&deltas[oA]   = dA; *(float4*)&deltas[oB]   = dB;
                        *(float4*)&partials[oA] = dA; *(float4*)&partials[oB] = dB;
                    }
                    a4.x = __fadd_rn(a4.x, dA.x); a4.y = __fadd_rn(a4.y, dA.y);
                    a4.z = __fadd_rn(a4.z, dA.z); a4.w = __fadd_rn(a4.w, dA.w);
                    b4.x = __fadd_rn(b4.x, dB.x); b4.y = __fadd_rn(b4.y, dB.y);
                    b4.z = __fadd_rn(b4.z, dB.z); b4.w = __fadd_rn(b4.w, dB.w);
                }
                u64* dst = &sx[(size_t)sp * SX_STRIDE + k0];
                ulonglong2 lo, hi;
                lo.x = pack2(a4.x, b4.x); lo.y = pack2(a4.y, b4.y);
                hi.x = pack2(a4.z, b4.z); hi.y = pack2(a4.w, b4.w);
                *(ulonglong2*)(dst)     = lo;
                *(ulonglong2*)(dst + 2) = hi;
            }
        }
        __syncthreads();

        // -------- compute: 1 pair x 2 cols, ascending-k chains --------------
        u64 acc0 = 0, acc1 = 0;               // cols nA, nA+1 (both lanes 0.0f)
        #pragma unroll 16
        for (int k2 = 0; k2 < 256; k2++) {
            ulonglong2 X = *(const ulonglong2*)(xr + 2 * k2);      // x_k, x_k+1
            float4 a = *(const float4*)&sA2[(size_t)(k2 * 16 + cp) * 4];
            ffma2(acc0, pack2(a.x, a.x), X.x);   // col nA,   k
            ffma2(acc1, pack2(a.z, a.z), X.x);   // col nA+1, k
            ffma2(acc0, pack2(a.y, a.y), X.y);   // col nA,   k+1
            ffma2(acc1, pack2(a.w, a.w), X.y);   // col nA+1, k+1
        }

        float z0a, z0b, z1a, z1b;
        unpack2(acc0, z0a, z0b);              // (bA,nA), (bB,nA)
        unpack2(acc1, z1a, z1b);              // (bA,nA+1), (bB,nA+1)
        const float h00 = tanh_xla(z0a);
        const float h10 = tanh_xla(z1a);
        const float h01 = tanh_xla(z0b);
        const float h11 = tanh_xla(z1b);

        // states writes: per batch, cols (nA, nA+1) adjacent -> STG.64
        float* so = states + ((size_t)t + 1) * NHID + nA;
        *(float2*)(so + (size_t)bA * Ll * NHID) = make_float2(h00, h10);
        *(float2*)(so + (size_t)bB * Ll * NHID) = make_float2(h01, h11);

        if (t == NSTEPS - 1 && nt == 0) {     // nA, nA+1 < 32 here
            size_t oA = ((size_t)bA * Ll + (Ll - 1)) * NOBS + nA;
            size_t oB = ((size_t)bB * Ll + (Ll - 1)) * NOBS + nA;
            size_t dIA = ((size_t)bA * Ll + (Ll - 2)) * NOBS + nA;
            size_t dIB = ((size_t)bB * Ll + (Ll - 2)) * NOBS + nA;
            exps[oA] = h00; exps[oA + 1] = h10;
            exps[oB] = h01; exps[oB + 1] = h11;
            float dAx = __fsub_rn(data[dIA],     h00);
            float dAy = __fsub_rn(data[dIA + 1], h10);
            float dBx = __fsub_rn(data[dIB],     h01);
            float dBy = __fsub_rn(data[dIB + 1], h11);
            deltas[oA] = dAx; deltas[oA + 1] = dAy;
            deltas[oB] = dBx; deltas[oB + 1] = dBy;
            partials[oA] = dAx; partials[oA + 1] = dAy;
            partials[oB] = dBx; partials[oB + 1] = dBy;
        }

        if (t < NSTEPS - 1)
            group_barrier(ctr, base + (u64)(t + 1) * GRP_CTAS);
    }
}

// ---------------------------------------------------------------------------
extern "C" void kernel_launch(void* const* d_in, const int* in_sizes, int n_in,
                              void* d_out, int out_size) {
    const float* data = (const float*)d_in[0];  // [128,2048,32]
    const float* A    = (const float*)d_in[1];  // [512,512]
    const float* h0   = (const float*)d_in[2];  // [1,512]
    // d_in[3] = prob (0) -> dropout identity

    float* out      = (float*)d_out;
    float* exps     = out;
    float* states   = exps   + (size_t)Bb * Ll * NOBS;
    float* deltas   = states + (size_t)Bb * Ll * NHID;
    float* partials = deltas + (size_t)Bb * Ll * NOBS;

    cudaFuncSetAttribute(ptf_persistent,
                         cudaFuncAttributeMaxDynamicSharedMemorySize, SMEM_BYTES);
    ptf_persistent<<<NCTA, NTHREADS, SMEM_BYTES>>>(data, A, h0,
                                                   exps, states, deltas, partials);
}